// round 2
// baseline (speedup 1.0000x reference)
#include <cuda_runtime.h>
#include <cuda_bf16.h>

#define N_NODES 65536
#define N_EDGES 65536
#define DF      128
#define NNZ_CNT (1 << 20)

// ---------------- scratch (device globals; no cudaMalloc allowed) ----------
__device__ int   g_cnt_n[N_NODES];
__device__ int   g_cnt_e[N_EDGES];
__device__ float g_degn[N_NODES];          // weighted node degree
__device__ float g_dinv[N_NODES];          // 1/deg_n
__device__ float g_se[N_EDGES];            // w_e / deg_e (folds B^-1 and w)
__device__ int   g_off_e[N_EDGES + 1];
__device__ int   g_off_n[N_NODES + 1];
__device__ int   g_cur_e[N_EDGES];
__device__ int   g_cur_n[N_NODES];
__device__ int   g_csr_e[NNZ_CNT];         // node ids grouped by edge
__device__ int   g_csr_n[NNZ_CNT];         // edge ids grouped by node
__device__ __align__(16) float g_y[N_NODES * DF];
__device__ __align__(16) float g_ef[N_EDGES * DF];
__device__ __align__(16) float g_h[N_NODES * DF];

// ---------------- kernels --------------------------------------------------
__global__ void k_zero() {
    int i = blockIdx.x * blockDim.x + threadIdx.x;
    if (i < N_NODES) { g_cnt_n[i] = 0; g_degn[i] = 0.f; }
    if (i < N_EDGES) { g_cnt_e[i] = 0; }
}

__global__ void k_hist(const int* __restrict__ nidx, const int* __restrict__ eidx,
                       const float* __restrict__ w) {
    int i = blockIdx.x * blockDim.x + threadIdx.x;
    if (i < NNZ_CNT) {
        int n = nidx[i];
        int e = eidx[i];
        atomicAdd(&g_cnt_n[n], 1);
        atomicAdd(&g_cnt_e[e], 1);
        atomicAdd(&g_degn[n], w[e]);
    }
}

// exclusive scan of 65536 ints with one 1024-thread block (64 elems/thread)
__global__ void k_scan(const int* __restrict__ cnt, int* __restrict__ off,
                       int* __restrict__ cur, int n) {
    __shared__ int ss[1024];
    int t = threadIdx.x;
    int per = n >> 10;             // 64
    int base = t * per;
    int s = 0;
    for (int i = 0; i < per; i++) s += cnt[base + i];
    ss[t] = s;
    __syncthreads();
    for (int d = 1; d < 1024; d <<= 1) {
        int v = (t >= d) ? ss[t - d] : 0;
        __syncthreads();
        ss[t] += v;
        __syncthreads();
    }
    int run = (t > 0) ? ss[t - 1] : 0;
    for (int i = 0; i < per; i++) {
        int c = cnt[base + i];
        off[base + i] = run;
        cur[base + i] = run;
        run += c;
    }
    if (t == 1023) off[n] = run;
}

__global__ void k_scales(const float* __restrict__ w) {
    int i = blockIdx.x * blockDim.x + threadIdx.x;
    if (i < N_EDGES) {
        int c = g_cnt_e[i];
        g_se[i] = (c > 0) ? (w[i] / (float)c) : 0.f;
    }
    if (i < N_NODES) {
        float d = g_degn[i];
        g_dinv[i] = (d > 0.f) ? (1.f / d) : 0.f;
    }
}

__global__ void k_build(const int* __restrict__ nidx, const int* __restrict__ eidx) {
    int i = blockIdx.x * blockDim.x + threadIdx.x;
    if (i < NNZ_CNT) {
        int n = nidx[i];
        int e = eidx[i];
        int p = atomicAdd(&g_cur_e[e], 1);
        g_csr_e[p] = n;
        int q = atomicAdd(&g_cur_n[n], 1);
        g_csr_n[q] = e;
    }
}

// C[row,:] = A[row,:] @ W   (A: [nrows,128], W: [128,128] row-major)
// block = 256 threads, 64 rows/block. smem: W(64KB) + Xtile(32KB) = 96KB.
__global__ void k_gemm(const float* __restrict__ A, const float* __restrict__ W,
                       float* __restrict__ C) {
    extern __shared__ float sm[];
    float4* sW4 = (float4*)sm;                 // 128*32 float4
    float4* sX4 = (float4*)(sm + DF * DF);     // 64*32 float4
    int tid = threadIdx.x;

    const float4* W4 = (const float4*)W;
    for (int i = tid; i < DF * DF / 4; i += 256) sW4[i] = W4[i];

    int row0 = blockIdx.x * 64;
    const float4* A4 = (const float4*)(A + (size_t)row0 * DF);
    for (int i = tid; i < 64 * DF / 4; i += 256) sX4[i] = A4[i];
    __syncthreads();

    int warp = tid >> 5, lane = tid & 31;
    float4 acc[8];
#pragma unroll
    for (int r = 0; r < 8; r++) acc[r] = make_float4(0.f, 0.f, 0.f, 0.f);

    for (int k0 = 0; k0 < DF; k0 += 4) {
        float4 w0 = sW4[(k0 + 0) * 32 + lane];
        float4 w1 = sW4[(k0 + 1) * 32 + lane];
        float4 w2 = sW4[(k0 + 2) * 32 + lane];
        float4 w3 = sW4[(k0 + 3) * 32 + lane];
#pragma unroll
        for (int r = 0; r < 8; r++) {
            float4 xv = sX4[(warp * 8 + r) * 32 + (k0 >> 2)];  // broadcast
            acc[r].x += xv.x * w0.x + xv.y * w1.x + xv.z * w2.x + xv.w * w3.x;
            acc[r].y += xv.x * w0.y + xv.y * w1.y + xv.z * w2.y + xv.w * w3.y;
            acc[r].z += xv.x * w0.z + xv.y * w1.z + xv.z * w2.z + xv.w * w3.z;
            acc[r].w += xv.x * w0.w + xv.y * w1.w + xv.z * w2.w + xv.w * w3.w;
        }
    }

    float4* C4 = (float4*)C;
#pragma unroll
    for (int r = 0; r < 8; r++)
        C4[(size_t)(row0 + warp * 8 + r) * 32 + lane] = acc[r];
}

// one warp per segment: dst[seg,:] = (sum_{j in seg} src[idx[j],:]) * scale[seg]
//                                    (+ bias) (relu?)
__global__ void k_agg(const float* __restrict__ src, float* __restrict__ dst,
                      const int* __restrict__ off, const int* __restrict__ idx,
                      const float* __restrict__ scale, const float* __restrict__ bias,
                      int relu, int nseg) {
    int gwarp = (blockIdx.x * blockDim.x + threadIdx.x) >> 5;
    int lane = threadIdx.x & 31;
    if (gwarp >= nseg) return;
    int s = off[gwarp], e = off[gwarp + 1];
    const float4* s4 = (const float4*)src;

    float4 a0 = make_float4(0.f, 0.f, 0.f, 0.f);
    float4 a1 = make_float4(0.f, 0.f, 0.f, 0.f);
    int j = s;
    for (; j + 1 < e; j += 2) {
        int r0 = idx[j];
        int r1 = idx[j + 1];
        float4 v0 = s4[(size_t)r0 * 32 + lane];
        float4 v1 = s4[(size_t)r1 * 32 + lane];
        a0.x += v0.x; a0.y += v0.y; a0.z += v0.z; a0.w += v0.w;
        a1.x += v1.x; a1.y += v1.y; a1.z += v1.z; a1.w += v1.w;
    }
    if (j < e) {
        int r = idx[j];
        float4 v = s4[(size_t)r * 32 + lane];
        a0.x += v.x; a0.y += v.y; a0.z += v.z; a0.w += v.w;
    }
    float sc = scale[gwarp];
    float4 o;
    o.x = (a0.x + a1.x) * sc;
    o.y = (a0.y + a1.y) * sc;
    o.z = (a0.z + a1.z) * sc;
    o.w = (a0.w + a1.w) * sc;
    if (bias) {
        float4 bb = ((const float4*)bias)[lane];
        o.x += bb.x; o.y += bb.y; o.z += bb.z; o.w += bb.w;
    }
    if (relu) {
        o.x = fmaxf(o.x, 0.f); o.y = fmaxf(o.y, 0.f);
        o.z = fmaxf(o.z, 0.f); o.w = fmaxf(o.w, 0.f);
    }
    ((float4*)dst)[(size_t)gwarp * 32 + lane] = o;
}

// ---------------- launch ---------------------------------------------------
extern "C" void kernel_launch(void* const* d_in, const int* in_sizes, int n_in,
                              void* d_out, int out_size) {
    const float* x   = (const float*)d_in[0];
    const int*   hei = (const int*)d_in[1];
    const float* w   = (const float*)d_in[2];
    const float* W1  = (const float*)d_in[3];
    const float* b1  = (const float*)d_in[4];
    const float* W2  = (const float*)d_in[5];
    const float* b2  = (const float*)d_in[6];
    float* out = (float*)d_out;

    const int* nidx = hei;
    const int* eidx = hei + NNZ_CNT;

    // resolve device-global addresses (host API, capture-safe)
    int *p_cnt_e, *p_cnt_n, *p_off_e, *p_off_n, *p_cur_e, *p_cur_n, *p_csr_e, *p_csr_n;
    float *p_y, *p_ef, *p_h, *p_se, *p_dinv;
    cudaGetSymbolAddress((void**)&p_cnt_e, g_cnt_e);
    cudaGetSymbolAddress((void**)&p_cnt_n, g_cnt_n);
    cudaGetSymbolAddress((void**)&p_off_e, g_off_e);
    cudaGetSymbolAddress((void**)&p_off_n, g_off_n);
    cudaGetSymbolAddress((void**)&p_cur_e, g_cur_e);
    cudaGetSymbolAddress((void**)&p_cur_n, g_cur_n);
    cudaGetSymbolAddress((void**)&p_csr_e, g_csr_e);
    cudaGetSymbolAddress((void**)&p_csr_n, g_csr_n);
    cudaGetSymbolAddress((void**)&p_y,    g_y);
    cudaGetSymbolAddress((void**)&p_ef,   g_ef);
    cudaGetSymbolAddress((void**)&p_h,    g_h);
    cudaGetSymbolAddress((void**)&p_se,   g_se);
    cudaGetSymbolAddress((void**)&p_dinv, g_dinv);

    cudaFuncSetAttribute(k_gemm, cudaFuncAttributeMaxDynamicSharedMemorySize, 98304);

    // -------- shared preprocessing (both layers use the same incidence) ----
    k_zero<<<256, 256>>>();
    k_hist<<<NNZ_CNT / 256, 256>>>(nidx, eidx, w);
    k_scan<<<1, 1024>>>(p_cnt_e, p_off_e, p_cur_e, N_EDGES);
    k_scan<<<1, 1024>>>(p_cnt_n, p_off_n, p_cur_n, N_NODES);
    k_scales<<<256, 256>>>(w);
    k_build<<<NNZ_CNT / 256, 256>>>(nidx, eidx);

    const int AGG_BLOCKS = N_NODES / 8;  // 8 warps per 256-thread block

    // -------- layer 1 ------------------------------------------------------
    k_gemm<<<N_NODES / 64, 256, 98304>>>(x, W1, p_y);
    k_agg<<<AGG_BLOCKS, 256>>>(p_y, p_ef, p_off_e, p_csr_e, p_se, nullptr, 0, N_EDGES);
    k_agg<<<AGG_BLOCKS, 256>>>(p_ef, p_h, p_off_n, p_csr_n, p_dinv, b1, 1, N_NODES);

    // -------- layer 2 ------------------------------------------------------
    k_gemm<<<N_NODES / 64, 256, 98304>>>(p_h, W2, p_y);
    k_agg<<<AGG_BLOCKS, 256>>>(p_y, p_ef, p_off_e, p_csr_e, p_se, nullptr, 0, N_EDGES);
    k_agg<<<AGG_BLOCKS, 256>>>(p_ef, out, p_off_n, p_csr_n, p_dinv, b2, 0, N_NODES);
}

// round 3
// speedup vs baseline: 1.8322x; 1.8322x over previous
#include <cuda_runtime.h>
#include <cuda_bf16.h>

#define N_NODES 65536
#define N_EDGES 65536
#define DF      128
#define NNZ_CNT (1 << 20)

// ---------------- scratch (device globals; no cudaMalloc allowed) ----------
__device__ int   g_cnt_n[N_NODES];
__device__ int   g_cnt_e[N_EDGES];
__device__ float g_degn[N_NODES];          // weighted node degree
__device__ float g_dinv[N_NODES];          // 1/deg_n
__device__ float g_se[N_EDGES];            // w_e / deg_e (folds B^-1 and w)
__device__ int   g_off_e[N_EDGES + 1];
__device__ int   g_off_n[N_NODES + 1];
__device__ int   g_cur_e[N_EDGES];
__device__ int   g_cur_n[N_NODES];
__device__ int   g_part[128];              // block partial sums (64 edge + 64 node)
__device__ int   g_csr_e[NNZ_CNT];         // node ids grouped by edge
__device__ int   g_csr_n[NNZ_CNT];         // edge ids grouped by node
__device__ __align__(16) float g_y[N_NODES * DF];
__device__ __align__(16) float g_ef[N_EDGES * DF];
__device__ __align__(16) float g_h[N_NODES * DF];

// ---------------- kernels --------------------------------------------------
__global__ void k_zero() {
    int i = blockIdx.x * blockDim.x + threadIdx.x;
    if (i < N_NODES) { g_cnt_n[i] = 0; g_degn[i] = 0.f; }
    if (i < N_EDGES) { g_cnt_e[i] = 0; }
}

__global__ void k_hist(const int* __restrict__ nidx, const int* __restrict__ eidx,
                       const float* __restrict__ w) {
    int i = blockIdx.x * blockDim.x + threadIdx.x;
    if (i < NNZ_CNT) {
        int n = nidx[i];
        int e = eidx[i];
        atomicAdd(&g_cnt_n[n], 1);
        atomicAdd(&g_cnt_e[e], 1);
        atomicAdd(&g_degn[n], w[e]);
    }
}

// ---- 3-phase parallel exclusive scan, both tables fused per launch --------
// Phase 1: 128 blocks x 1024 threads. Blocks 0-63 scan cnt_e, 64-127 cnt_n.
// Writes block-local exclusive scan into off[], block total into g_part[b].
__global__ void k_scan1() {
    int b = blockIdx.x;
    bool edge = b < 64;
    const int* __restrict__ cnt = edge ? g_cnt_e : g_cnt_n;
    int* __restrict__ off = edge ? g_off_e : g_off_n;
    int lb = edge ? b : b - 64;
    int i = lb * 1024 + threadIdx.x;
    int lane = threadIdx.x & 31, wid = threadIdx.x >> 5;

    int c = cnt[i];
    int v = c;
#pragma unroll
    for (int d = 1; d < 32; d <<= 1) {
        int t = __shfl_up_sync(~0u, v, d);
        if (lane >= d) v += t;
    }
    __shared__ int ws[32];
    if (lane == 31) ws[wid] = v;
    __syncthreads();
    if (wid == 0) {
        int s = ws[lane];
#pragma unroll
        for (int d = 1; d < 32; d <<= 1) {
            int t = __shfl_up_sync(~0u, s, d);
            if (lane >= d) s += t;
        }
        ws[lane] = s;
    }
    __syncthreads();
    int excl = v - c + (wid > 0 ? ws[wid - 1] : 0);
    off[i] = excl;                                   // local; fixed up in phase 3
    if (threadIdx.x == 1023) g_part[b] = excl + c;   // block total
}

// Phase 2: one block, 128 threads; two independent 64-wide segmented scans.
__global__ void k_scan2() {
    __shared__ int ss[128];
    int t = threadIdx.x;
    int seg = t & 63;
    ss[t] = g_part[t];
    __syncthreads();
#pragma unroll
    for (int d = 1; d < 64; d <<= 1) {
        int v = (seg >= d) ? ss[t - d] : 0;
        __syncthreads();
        ss[t] += v;
        __syncthreads();
    }
    g_part[t] = (seg > 0) ? ss[t - 1] : 0;           // exclusive block base
}

// Phase 3: add block base, write off/cur, and compute se/dinv (fused scales).
__global__ void k_scan3(const float* __restrict__ w) {
    int b = blockIdx.x;
    bool edge = b < 64;
    int* __restrict__ off = edge ? g_off_e : g_off_n;
    int* __restrict__ cur = edge ? g_cur_e : g_cur_n;
    int lb = edge ? b : b - 64;
    int i = lb * 1024 + threadIdx.x;
    int base = g_part[b];
    int v = off[i] + base;
    off[i] = v;
    cur[i] = v;
    if (edge) {
        int c = g_cnt_e[i];
        g_se[i] = (c > 0) ? (w[i] / (float)c) : 0.f;
    } else {
        float d = g_degn[i];
        g_dinv[i] = (d > 0.f) ? (1.f / d) : 0.f;
    }
    if (b == 0 && threadIdx.x == 0) {
        g_off_e[N_EDGES] = NNZ_CNT;
        g_off_n[N_NODES] = NNZ_CNT;
    }
}

__global__ void k_build(const int* __restrict__ nidx, const int* __restrict__ eidx) {
    int i = blockIdx.x * blockDim.x + threadIdx.x;
    if (i < NNZ_CNT) {
        int n = nidx[i];
        int e = eidx[i];
        int p = atomicAdd(&g_cur_e[e], 1);
        g_csr_e[p] = n;
        int q = atomicAdd(&g_cur_n[n], 1);
        g_csr_n[q] = e;
    }
}

// C[row,:] = A[row,:] @ W   (A: [nrows,128], W: [128,128] row-major)
// block = 256 threads, 64 rows/block. smem: W(64KB) + Xtile(32KB) = 96KB.
__global__ void k_gemm(const float* __restrict__ A, const float* __restrict__ W,
                       float* __restrict__ C) {
    extern __shared__ float sm[];
    float4* sW4 = (float4*)sm;                 // 128*32 float4
    float4* sX4 = (float4*)(sm + DF * DF);     // 64*32 float4
    int tid = threadIdx.x;

    const float4* W4 = (const float4*)W;
    for (int i = tid; i < DF * DF / 4; i += 256) sW4[i] = W4[i];

    int row0 = blockIdx.x * 64;
    const float4* A4 = (const float4*)(A + (size_t)row0 * DF);
    for (int i = tid; i < 64 * DF / 4; i += 256) sX4[i] = A4[i];
    __syncthreads();

    int warp = tid >> 5, lane = tid & 31;
    float4 acc[8];
#pragma unroll
    for (int r = 0; r < 8; r++) acc[r] = make_float4(0.f, 0.f, 0.f, 0.f);

    for (int k0 = 0; k0 < DF; k0 += 4) {
        float4 w0 = sW4[(k0 + 0) * 32 + lane];
        float4 w1 = sW4[(k0 + 1) * 32 + lane];
        float4 w2 = sW4[(k0 + 2) * 32 + lane];
        float4 w3 = sW4[(k0 + 3) * 32 + lane];
#pragma unroll
        for (int r = 0; r < 8; r++) {
            float4 xv = sX4[(warp * 8 + r) * 32 + (k0 >> 2)];  // broadcast
            acc[r].x += xv.x * w0.x + xv.y * w1.x + xv.z * w2.x + xv.w * w3.x;
            acc[r].y += xv.x * w0.y + xv.y * w1.y + xv.z * w2.y + xv.w * w3.y;
            acc[r].z += xv.x * w0.z + xv.y * w1.z + xv.z * w2.z + xv.w * w3.z;
            acc[r].w += xv.x * w0.w + xv.y * w1.w + xv.z * w2.w + xv.w * w3.w;
        }
    }

    float4* C4 = (float4*)C;
#pragma unroll
    for (int r = 0; r < 8; r++)
        C4[(size_t)(row0 + warp * 8 + r) * 32 + lane] = acc[r];
}

// one warp per segment: dst[seg,:] = (sum_{j in seg} src[idx[j],:]) * scale[seg]
//                                    (+ bias) (relu?)
__global__ void k_agg(const float* __restrict__ src, float* __restrict__ dst,
                      const int* __restrict__ off, const int* __restrict__ idx,
                      const float* __restrict__ scale, const float* __restrict__ bias,
                      int relu, int nseg) {
    int gwarp = (blockIdx.x * blockDim.x + threadIdx.x) >> 5;
    int lane = threadIdx.x & 31;
    if (gwarp >= nseg) return;
    int s = off[gwarp], e = off[gwarp + 1];
    const float4* s4 = (const float4*)src;

    float4 a0 = make_float4(0.f, 0.f, 0.f, 0.f);
    float4 a1 = make_float4(0.f, 0.f, 0.f, 0.f);
    int j = s;
    for (; j + 1 < e; j += 2) {
        int r0 = idx[j];
        int r1 = idx[j + 1];
        float4 v0 = s4[(size_t)r0 * 32 + lane];
        float4 v1 = s4[(size_t)r1 * 32 + lane];
        a0.x += v0.x; a0.y += v0.y; a0.z += v0.z; a0.w += v0.w;
        a1.x += v1.x; a1.y += v1.y; a1.z += v1.z; a1.w += v1.w;
    }
    if (j < e) {
        int r = idx[j];
        float4 v = s4[(size_t)r * 32 + lane];
        a0.x += v.x; a0.y += v.y; a0.z += v.z; a0.w += v.w;
    }
    float sc = scale[gwarp];
    float4 o;
    o.x = (a0.x + a1.x) * sc;
    o.y = (a0.y + a1.y) * sc;
    o.z = (a0.z + a1.z) * sc;
    o.w = (a0.w + a1.w) * sc;
    if (bias) {
        float4 bb = ((const float4*)bias)[lane];
        o.x += bb.x; o.y += bb.y; o.z += bb.z; o.w += bb.w;
    }
    if (relu) {
        o.x = fmaxf(o.x, 0.f); o.y = fmaxf(o.y, 0.f);
        o.z = fmaxf(o.z, 0.f); o.w = fmaxf(o.w, 0.f);
    }
    ((float4*)dst)[(size_t)gwarp * 32 + lane] = o;
}

// ---------------- launch ---------------------------------------------------
extern "C" void kernel_launch(void* const* d_in, const int* in_sizes, int n_in,
                              void* d_out, int out_size) {
    const float* x   = (const float*)d_in[0];
    const int*   hei = (const int*)d_in[1];
    const float* w   = (const float*)d_in[2];
    const float* W1  = (const float*)d_in[3];
    const float* b1  = (const float*)d_in[4];
    const float* W2  = (const float*)d_in[5];
    const float* b2  = (const float*)d_in[6];
    float* out = (float*)d_out;

    const int* nidx = hei;
    const int* eidx = hei + NNZ_CNT;

    // resolve device-global addresses (host API, capture-safe)
    int *p_off_e, *p_off_n, *p_csr_e, *p_csr_n;
    float *p_y, *p_ef, *p_h, *p_se, *p_dinv;
    cudaGetSymbolAddress((void**)&p_off_e, g_off_e);
    cudaGetSymbolAddress((void**)&p_off_n, g_off_n);
    cudaGetSymbolAddress((void**)&p_csr_e, g_csr_e);
    cudaGetSymbolAddress((void**)&p_csr_n, g_csr_n);
    cudaGetSymbolAddress((void**)&p_y,    g_y);
    cudaGetSymbolAddress((void**)&p_ef,   g_ef);
    cudaGetSymbolAddress((void**)&p_h,    g_h);
    cudaGetSymbolAddress((void**)&p_se,   g_se);
    cudaGetSymbolAddress((void**)&p_dinv, g_dinv);

    cudaFuncSetAttribute(k_gemm, cudaFuncAttributeMaxDynamicSharedMemorySize, 98304);

    // -------- shared preprocessing (both layers use the same incidence) ----
    k_zero<<<256, 256>>>();
    k_hist<<<NNZ_CNT / 256, 256>>>(nidx, eidx, w);
    k_scan1<<<128, 1024>>>();
    k_scan2<<<1, 128>>>();
    k_scan3<<<128, 1024>>>(w);
    k_build<<<NNZ_CNT / 256, 256>>>(nidx, eidx);

    const int AGG_BLOCKS = N_NODES / 8;  // 8 warps per 256-thread block

    // -------- layer 1 ------------------------------------------------------
    k_gemm<<<N_NODES / 64, 256, 98304>>>(x, W1, p_y);
    k_agg<<<AGG_BLOCKS, 256>>>(p_y, p_ef, p_off_e, p_csr_e, p_se, nullptr, 0, N_EDGES);
    k_agg<<<AGG_BLOCKS, 256>>>(p_ef, p_h, p_off_n, p_csr_n, p_dinv, b1, 1, N_NODES);

    // -------- layer 2 ------------------------------------------------------
    k_gemm<<<N_NODES / 64, 256, 98304>>>(p_h, W2, p_y);
    k_agg<<<AGG_BLOCKS, 256>>>(p_y, p_ef, p_off_e, p_csr_e, p_se, nullptr, 0, N_EDGES);
    k_agg<<<AGG_BLOCKS, 256>>>(p_ef, out, p_off_n, p_csr_n, p_dinv, b2, 0, N_NODES);
}

// round 4
// speedup vs baseline: 2.2219x; 1.2127x over previous
#include <cuda_runtime.h>
#include <cuda_fp16.h>
#include <cuda_bf16.h>

#define N_NODES 65536
#define N_EDGES 65536
#define DF      128
#define NNZ_CNT (1 << 20)

// ---------------- scratch (device globals; no cudaMalloc allowed) ----------
__device__ int   g_cnt_n[N_NODES];
__device__ int   g_cnt_e[N_EDGES];
__device__ float g_degn[N_NODES];          // weighted node degree
__device__ float g_dinv[N_NODES];          // 1/deg_n
__device__ float g_se[N_EDGES];            // w_e / deg_e (folds B^-1 and w)
__device__ int   g_off_e[N_EDGES + 1];
__device__ int   g_off_n[N_NODES + 1];
__device__ int   g_cur_e[N_EDGES];
__device__ int   g_cur_n[N_NODES];
__device__ int   g_part[128];              // block partial sums (64 edge + 64 node)
__device__ int   g_csr_e[NNZ_CNT];         // node ids grouped by edge
__device__ int   g_csr_n[NNZ_CNT];         // edge ids grouped by node
__device__ __align__(16) __half g_y_h[N_NODES * DF];   // GEMM out (fp16)
__device__ __align__(16) __half g_ef_h[N_EDGES * DF];  // edge features (fp16)
__device__ __align__(16) float  g_h[N_NODES * DF];     // hidden (fp32, GEMM input)

// ---------------- preprocessing kernels ------------------------------------
__global__ void k_zero() {
    int i = blockIdx.x * blockDim.x + threadIdx.x;
    if (i < N_NODES) { g_cnt_n[i] = 0; g_degn[i] = 0.f; }
    if (i < N_EDGES) { g_cnt_e[i] = 0; }
}

__global__ void k_hist(const int* __restrict__ nidx, const int* __restrict__ eidx,
                       const float* __restrict__ w) {
    int i = blockIdx.x * blockDim.x + threadIdx.x;
    if (i < NNZ_CNT) {
        int n = nidx[i];
        int e = eidx[i];
        atomicAdd(&g_cnt_n[n], 1);
        atomicAdd(&g_cnt_e[e], 1);
        atomicAdd(&g_degn[n], w[e]);
    }
}

// ---- 3-phase parallel exclusive scan, both tables fused per launch --------
__global__ void k_scan1() {
    int b = blockIdx.x;
    bool edge = b < 64;
    const int* __restrict__ cnt = edge ? g_cnt_e : g_cnt_n;
    int* __restrict__ off = edge ? g_off_e : g_off_n;
    int lb = edge ? b : b - 64;
    int i = lb * 1024 + threadIdx.x;
    int lane = threadIdx.x & 31, wid = threadIdx.x >> 5;

    int c = cnt[i];
    int v = c;
#pragma unroll
    for (int d = 1; d < 32; d <<= 1) {
        int t = __shfl_up_sync(~0u, v, d);
        if (lane >= d) v += t;
    }
    __shared__ int ws[32];
    if (lane == 31) ws[wid] = v;
    __syncthreads();
    if (wid == 0) {
        int s = ws[lane];
#pragma unroll
        for (int d = 1; d < 32; d <<= 1) {
            int t = __shfl_up_sync(~0u, s, d);
            if (lane >= d) s += t;
        }
        ws[lane] = s;
    }
    __syncthreads();
    int excl = v - c + (wid > 0 ? ws[wid - 1] : 0);
    off[i] = excl;
    if (threadIdx.x == 1023) g_part[b] = excl + c;
}

__global__ void k_scan2() {
    __shared__ int ss[128];
    int t = threadIdx.x;
    int seg = t & 63;
    ss[t] = g_part[t];
    __syncthreads();
#pragma unroll
    for (int d = 1; d < 64; d <<= 1) {
        int v = (seg >= d) ? ss[t - d] : 0;
        __syncthreads();
        ss[t] += v;
        __syncthreads();
    }
    g_part[t] = (seg > 0) ? ss[t - 1] : 0;
}

__global__ void k_scan3(const float* __restrict__ w) {
    int b = blockIdx.x;
    bool edge = b < 64;
    int* __restrict__ off = edge ? g_off_e : g_off_n;
    int* __restrict__ cur = edge ? g_cur_e : g_cur_n;
    int lb = edge ? b : b - 64;
    int i = lb * 1024 + threadIdx.x;
    int base = g_part[b];
    int v = off[i] + base;
    off[i] = v;
    cur[i] = v;
    if (edge) {
        int c = g_cnt_e[i];
        g_se[i] = (c > 0) ? (w[i] / (float)c) : 0.f;
    } else {
        float d = g_degn[i];
        g_dinv[i] = (d > 0.f) ? (1.f / d) : 0.f;
    }
    if (b == 0 && threadIdx.x == 0) {
        g_off_e[N_EDGES] = NNZ_CNT;
        g_off_n[N_NODES] = NNZ_CNT;
    }
}

__global__ void k_build(const int* __restrict__ nidx, const int* __restrict__ eidx) {
    int i = blockIdx.x * blockDim.x + threadIdx.x;
    if (i < NNZ_CNT) {
        int n = nidx[i];
        int e = eidx[i];
        int p = atomicAdd(&g_cur_e[e], 1);
        g_csr_e[p] = n;
        int q = atomicAdd(&g_cur_n[n], 1);
        g_csr_n[q] = e;
    }
}

// ---------------- f32x2 GEMM ------------------------------------------------
// C[row,0:128] = A[row,0:128] @ W, output fp16.
// smem: W staged as (even-k, odd-k) packed pairs -> zero pack instructions.
//   sWpA[kp*32+l] = float4( W[2kp][4l],  W[2kp+1][4l],  W[2kp][4l+1], W[2kp+1][4l+1] )
//   sWpB[kp*32+l] = same for cols 4l+2, 4l+3
// Lane owns output cols 4l..4l+3; accumulators are f32x2 (even-k, odd-k partials).
#define FMA2(acc, x, w) \
    asm("fma.rn.f32x2 %0, %1, %2, %0;" : "+l"(acc) : "l"(x), "l"(w))

__global__ void __launch_bounds__(256) k_gemm(const float* __restrict__ A,
                                              const float* __restrict__ W,
                                              __half* __restrict__ C) {
    extern __shared__ float sm[];
    float* sWA = sm;                 // 8192 floats (32KB): 64 kp * 32 lanes * 4
    float* sWB = sm + 8192;          // 8192 floats (32KB)
    float4* sX4 = (float4*)(sm + 16384);  // 64 rows * 32 float4 (32KB)
    int tid = threadIdx.x;

    // stage W: coalesced float4 reads, scalar smem scatter into pair layout
    const float4* W4 = (const float4*)W;
    for (int i = tid; i < 4096; i += 256) {
        float4 v = W4[i];
        int k = i >> 5;            // W row (k index)
        int l = i & 31;            // lane / col group
        int kp = k >> 1, ko = k & 1;
        float* dA = &sWA[(kp * 32 + l) * 4];
        float* dB = &sWB[(kp * 32 + l) * 4];
        dA[ko]     = v.x;  // col 4l
        dA[2 + ko] = v.y;  // col 4l+1
        dB[ko]     = v.z;  // col 4l+2
        dB[2 + ko] = v.w;  // col 4l+3
    }

    int row0 = blockIdx.x * 64;
    const float4* A4 = (const float4*)(A + (size_t)row0 * DF);
    for (int i = tid; i < 64 * DF / 4; i += 256) sX4[i] = A4[i];
    __syncthreads();

    int warp = tid >> 5, lane = tid & 31;
    unsigned long long acc[8][4];
#pragma unroll
    for (int r = 0; r < 8; r++)
#pragma unroll
        for (int c = 0; c < 4; c++) acc[r][c] = 0ULL;

    const ulonglong2* sXp = (const ulonglong2*)sX4;
    const ulonglong2* sA2 = (const ulonglong2*)sWA;
    const ulonglong2* sB2 = (const ulonglong2*)sWB;

#pragma unroll 4
    for (int k0 = 0; k0 < DF; k0 += 4) {
        int kp0 = k0 >> 1;
        ulonglong2 wa0 = sA2[kp0 * 32 + lane];        // cols 4l,4l+1 @ k-pair kp0
        ulonglong2 wb0 = sB2[kp0 * 32 + lane];        // cols 4l+2,4l+3
        ulonglong2 wa1 = sA2[(kp0 + 1) * 32 + lane];  // k-pair kp0+1
        ulonglong2 wb1 = sB2[(kp0 + 1) * 32 + lane];
#pragma unroll
        for (int r = 0; r < 8; r++) {
            ulonglong2 xp = sXp[(warp * 8 + r) * 32 + (k0 >> 2)];  // broadcast
            FMA2(acc[r][0], xp.x, wa0.x);
            FMA2(acc[r][1], xp.x, wa0.y);
            FMA2(acc[r][2], xp.x, wb0.x);
            FMA2(acc[r][3], xp.x, wb0.y);
            FMA2(acc[r][0], xp.y, wa1.x);
            FMA2(acc[r][1], xp.y, wa1.y);
            FMA2(acc[r][2], xp.y, wb1.x);
            FMA2(acc[r][3], xp.y, wb1.y);
        }
    }

    uint2* C2 = (uint2*)C;
#pragma unroll
    for (int r = 0; r < 8; r++) {
        float2 p0 = *(float2*)&acc[r][0];
        float2 p1 = *(float2*)&acc[r][1];
        float2 p2 = *(float2*)&acc[r][2];
        float2 p3 = *(float2*)&acc[r][3];
        __half2 h01 = __floats2half2_rn(p0.x + p0.y, p1.x + p1.y);
        __half2 h23 = __floats2half2_rn(p2.x + p2.y, p3.x + p3.y);
        uint2 st;
        st.x = *(unsigned*)&h01;
        st.y = *(unsigned*)&h23;
        C2[(size_t)(row0 + warp * 8 + r) * 32 + lane] = st;
    }
}

// ---------------- segment aggregation (gather, one warp per segment) -------
// dst[seg,:] = (sum src[idx[j],:]) * scale[seg] (+bias) (relu)
// src is fp16 [*,128]; lane owns cols 4l..4l+3 (uint2 = 4 halves).
template<int OUT_HALF, int RELU, int HAS_BIAS>
__global__ void k_agg(const __half* __restrict__ src, void* __restrict__ dst,
                      const int* __restrict__ off, const int* __restrict__ idx,
                      const float* __restrict__ scale, const float* __restrict__ bias,
                      int nseg) {
    int gwarp = (blockIdx.x * blockDim.x + threadIdx.x) >> 5;
    int lane = threadIdx.x & 31;
    if (gwarp >= nseg) return;
    int s = off[gwarp], e = off[gwarp + 1];
    const uint2* s2 = (const uint2*)src;

    float4 a0 = make_float4(0.f, 0.f, 0.f, 0.f);
    float4 a1 = make_float4(0.f, 0.f, 0.f, 0.f);
    int j = s;
    for (; j + 1 < e; j += 2) {
        int r0 = idx[j];
        int r1 = idx[j + 1];
        uint2 u0 = s2[(size_t)r0 * 32 + lane];
        uint2 u1 = s2[(size_t)r1 * 32 + lane];
        float2 f00 = __half22float2(*(const __half2*)&u0.x);
        float2 f01 = __half22float2(*(const __half2*)&u0.y);
        float2 f10 = __half22float2(*(const __half2*)&u1.x);
        float2 f11 = __half22float2(*(const __half2*)&u1.y);
        a0.x += f00.x; a0.y += f00.y; a0.z += f01.x; a0.w += f01.y;
        a1.x += f10.x; a1.y += f10.y; a1.z += f11.x; a1.w += f11.y;
    }
    if (j < e) {
        int r = idx[j];
        uint2 u = s2[(size_t)r * 32 + lane];
        float2 f0 = __half22float2(*(const __half2*)&u.x);
        float2 f1 = __half22float2(*(const __half2*)&u.y);
        a0.x += f0.x; a0.y += f0.y; a0.z += f1.x; a0.w += f1.y;
    }
    float sc = scale[gwarp];
    float4 o;
    o.x = (a0.x + a1.x) * sc;
    o.y = (a0.y + a1.y) * sc;
    o.z = (a0.z + a1.z) * sc;
    o.w = (a0.w + a1.w) * sc;
    if (HAS_BIAS) {
        float4 bb = ((const float4*)bias)[lane];
        o.x += bb.x; o.y += bb.y; o.z += bb.z; o.w += bb.w;
    }
    if (RELU) {
        o.x = fmaxf(o.x, 0.f); o.y = fmaxf(o.y, 0.f);
        o.z = fmaxf(o.z, 0.f); o.w = fmaxf(o.w, 0.f);
    }
    if (OUT_HALF) {
        __half2 h01 = __floats2half2_rn(o.x, o.y);
        __half2 h23 = __floats2half2_rn(o.z, o.w);
        uint2 st;
        st.x = *(unsigned*)&h01;
        st.y = *(unsigned*)&h23;
        ((uint2*)dst)[(size_t)gwarp * 32 + lane] = st;
    } else {
        ((float4*)dst)[(size_t)gwarp * 32 + lane] = o;
    }
}

// ---------------- launch ---------------------------------------------------
extern "C" void kernel_launch(void* const* d_in, const int* in_sizes, int n_in,
                              void* d_out, int out_size) {
    const float* x   = (const float*)d_in[0];
    const int*   hei = (const int*)d_in[1];
    const float* w   = (const float*)d_in[2];
    const float* W1  = (const float*)d_in[3];
    const float* b1  = (const float*)d_in[4];
    const float* W2  = (const float*)d_in[5];
    const float* b2  = (const float*)d_in[6];
    float* out = (float*)d_out;

    const int* nidx = hei;
    const int* eidx = hei + NNZ_CNT;

    int *p_off_e, *p_off_n, *p_csr_e, *p_csr_n;
    float *p_h, *p_se, *p_dinv;
    __half *p_y, *p_ef;
    cudaGetSymbolAddress((void**)&p_off_e, g_off_e);
    cudaGetSymbolAddress((void**)&p_off_n, g_off_n);
    cudaGetSymbolAddress((void**)&p_csr_e, g_csr_e);
    cudaGetSymbolAddress((void**)&p_csr_n, g_csr_n);
    cudaGetSymbolAddress((void**)&p_y,    g_y_h);
    cudaGetSymbolAddress((void**)&p_ef,   g_ef_h);
    cudaGetSymbolAddress((void**)&p_h,    g_h);
    cudaGetSymbolAddress((void**)&p_se,   g_se);
    cudaGetSymbolAddress((void**)&p_dinv, g_dinv);

    cudaFuncSetAttribute(k_gemm, cudaFuncAttributeMaxDynamicSharedMemorySize, 98304);

    // -------- shared preprocessing -----------------------------------------
    k_zero<<<256, 256>>>();
    k_hist<<<NNZ_CNT / 256, 256>>>(nidx, eidx, w);
    k_scan1<<<128, 1024>>>();
    k_scan2<<<1, 128>>>();
    k_scan3<<<128, 1024>>>(w);
    k_build<<<NNZ_CNT / 256, 256>>>(nidx, eidx);

    const int AGG_BLOCKS = N_NODES / 8;  // 8 warps per 256-thread block

    // -------- layer 1 ------------------------------------------------------
    k_gemm<<<N_NODES / 64, 256, 98304>>>(x, W1, p_y);
    k_agg<1, 0, 0><<<AGG_BLOCKS, 256>>>(p_y, p_ef, p_off_e, p_csr_e, p_se, nullptr, N_EDGES);
    k_agg<0, 1, 1><<<AGG_BLOCKS, 256>>>(p_ef, p_h, p_off_n, p_csr_n, p_dinv, b1, N_NODES);

    // -------- layer 2 ------------------------------------------------------
    k_gemm<<<N_NODES / 64, 256, 98304>>>(p_h, W2, p_y);
    k_agg<1, 0, 0><<<AGG_BLOCKS, 256>>>(p_y, p_ef, p_off_e, p_csr_e, p_se, nullptr, N_EDGES);
    k_agg<0, 0, 1><<<AGG_BLOCKS, 256>>>(p_ef, out, p_off_n, p_csr_n, p_dinv, b2, N_NODES);
}

// round 5
// speedup vs baseline: 2.8346x; 1.2758x over previous
#include <cuda_runtime.h>
#include <cuda_fp16.h>
#include <cuda_bf16.h>

#define N_NODES 65536
#define N_EDGES 65536
#define DF      128
#define NNZ_CNT (1 << 20)
#define LDA     136   // smem row stride in halves: 272B, mod 128 = 16 -> conflict-free ldmatrix

// ---------------- scratch (device globals; no cudaMalloc allowed) ----------
__device__ int   g_cnt_n[N_NODES];
__device__ int   g_cnt_e[N_EDGES];
__device__ float g_degn[N_NODES];
__device__ float g_dinv[N_NODES];
__device__ float g_se[N_EDGES];
__device__ int   g_off_e[N_EDGES + 1];
__device__ int   g_off_n[N_NODES + 1];
__device__ int   g_cur_e[N_EDGES];
__device__ int   g_cur_n[N_NODES];
__device__ int   g_part[128];
__device__ int   g_csr_e[NNZ_CNT];
__device__ int   g_csr_n[NNZ_CNT];
__device__ __align__(16) __half g_y_h[N_NODES * DF];   // GEMM out (fp16)
__device__ __align__(16) __half g_ef_h[N_EDGES * DF];  // edge features (fp16)
__device__ __align__(16) __half g_h_h[N_NODES * DF];   // hidden (fp16)

// ---------------- preprocessing kernels ------------------------------------
__global__ void k_zero() {
    int i = blockIdx.x * blockDim.x + threadIdx.x;
    if (i < N_NODES) { g_cnt_n[i] = 0; g_degn[i] = 0.f; }
    if (i < N_EDGES) { g_cnt_e[i] = 0; }
}

__global__ void k_hist(const int* __restrict__ nidx, const int* __restrict__ eidx,
                       const float* __restrict__ w) {
    int i = blockIdx.x * blockDim.x + threadIdx.x;
    if (i < NNZ_CNT) {
        int n = nidx[i];
        int e = eidx[i];
        atomicAdd(&g_cnt_n[n], 1);
        atomicAdd(&g_cnt_e[e], 1);
        atomicAdd(&g_degn[n], w[e]);
    }
}

__global__ void k_scan1() {
    int b = blockIdx.x;
    bool edge = b < 64;
    const int* __restrict__ cnt = edge ? g_cnt_e : g_cnt_n;
    int* __restrict__ off = edge ? g_off_e : g_off_n;
    int lb = edge ? b : b - 64;
    int i = lb * 1024 + threadIdx.x;
    int lane = threadIdx.x & 31, wid = threadIdx.x >> 5;

    int c = cnt[i];
    int v = c;
#pragma unroll
    for (int d = 1; d < 32; d <<= 1) {
        int t = __shfl_up_sync(~0u, v, d);
        if (lane >= d) v += t;
    }
    __shared__ int ws[32];
    if (lane == 31) ws[wid] = v;
    __syncthreads();
    if (wid == 0) {
        int s = ws[lane];
#pragma unroll
        for (int d = 1; d < 32; d <<= 1) {
            int t = __shfl_up_sync(~0u, s, d);
            if (lane >= d) s += t;
        }
        ws[lane] = s;
    }
    __syncthreads();
    int excl = v - c + (wid > 0 ? ws[wid - 1] : 0);
    off[i] = excl;
    if (threadIdx.x == 1023) g_part[b] = excl + c;
}

__global__ void k_scan2() {
    __shared__ int ss[128];
    int t = threadIdx.x;
    int seg = t & 63;
    ss[t] = g_part[t];
    __syncthreads();
#pragma unroll
    for (int d = 1; d < 64; d <<= 1) {
        int v = (seg >= d) ? ss[t - d] : 0;
        __syncthreads();
        ss[t] += v;
        __syncthreads();
    }
    g_part[t] = (seg > 0) ? ss[t - 1] : 0;
}

__global__ void k_scan3(const float* __restrict__ w) {
    int b = blockIdx.x;
    bool edge = b < 64;
    int* __restrict__ off = edge ? g_off_e : g_off_n;
    int* __restrict__ cur = edge ? g_cur_e : g_cur_n;
    int lb = edge ? b : b - 64;
    int i = lb * 1024 + threadIdx.x;
    int base = g_part[b];
    int v = off[i] + base;
    off[i] = v;
    cur[i] = v;
    if (edge) {
        int c = g_cnt_e[i];
        g_se[i] = (c > 0) ? (w[i] / (float)c) : 0.f;
    } else {
        float d = g_degn[i];
        g_dinv[i] = (d > 0.f) ? (1.f / d) : 0.f;
    }
    if (b == 0 && threadIdx.x == 0) {
        g_off_e[N_EDGES] = NNZ_CNT;
        g_off_n[N_NODES] = NNZ_CNT;
    }
}

__global__ void k_build(const int* __restrict__ nidx, const int* __restrict__ eidx) {
    int i = blockIdx.x * blockDim.x + threadIdx.x;
    if (i < NNZ_CNT) {
        int n = nidx[i];
        int e = eidx[i];
        int p = atomicAdd(&g_cur_e[e], 1);
        g_csr_e[p] = n;
        int q = atomicAdd(&g_cur_n[n], 1);
        g_csr_n[q] = e;
    }
}

// ---------------- HMMA GEMM -------------------------------------------------
// C[row0:row0+128, 0:128] = A @ W (both converted to fp16, fp32 accumulate).
// 256 threads = 8 warps; warp w computes rows w*16..w*16+15, all 128 cols.
__device__ __forceinline__ void ldsm_x4(unsigned& r0, unsigned& r1, unsigned& r2,
                                        unsigned& r3, unsigned addr) {
    asm volatile("ldmatrix.sync.aligned.m8n8.x4.shared.b16 {%0,%1,%2,%3}, [%4];"
                 : "=r"(r0), "=r"(r1), "=r"(r2), "=r"(r3) : "r"(addr));
}
__device__ __forceinline__ void ldsm_x4t(unsigned& r0, unsigned& r1, unsigned& r2,
                                         unsigned& r3, unsigned addr) {
    asm volatile("ldmatrix.sync.aligned.m8n8.x4.trans.shared.b16 {%0,%1,%2,%3}, [%4];"
                 : "=r"(r0), "=r"(r1), "=r"(r2), "=r"(r3) : "r"(addr));
}
#define MMA16816(c, a0, a1, a2, a3, b0, b1) \
    asm volatile("mma.sync.aligned.m16n8k16.row.col.f32.f16.f16.f32 " \
                 "{%0,%1,%2,%3}, {%4,%5,%6,%7}, {%8,%9}, {%0,%1,%2,%3};" \
                 : "+f"(c[0]), "+f"(c[1]), "+f"(c[2]), "+f"(c[3]) \
                 : "r"(a0), "r"(a1), "r"(a2), "r"(a3), "r"(b0), "r"(b1))

template<int A_FP16>
__global__ void __launch_bounds__(256) k_gemm_mma(const void* __restrict__ Aptr,
                                                  const float* __restrict__ W,
                                                  __half* __restrict__ C) {
    extern __shared__ __half smh[];
    __half* sA = smh;               // 128 x LDA
    __half* sB = smh + 128 * LDA;   // 128 x LDA (W, k-major rows)
    int tid = threadIdx.x;
    int row0 = blockIdx.x * 128;

    // stage W: fp32 -> fp16
    const float4* W4 = (const float4*)W;
    for (int i = tid; i < 4096; i += 256) {
        float4 v = W4[i];
        int k = i >> 5, n = (i & 31) * 4;
        __half2* d = (__half2*)&sB[k * LDA + n];
        d[0] = __floats2half2_rn(v.x, v.y);
        d[1] = __floats2half2_rn(v.z, v.w);
    }
    // stage A
    if (A_FP16) {
        const uint4* A4 = (const uint4*)((const __half*)Aptr + (size_t)row0 * DF);
        for (int i = tid; i < 128 * DF / 8; i += 256) {
            int r = i >> 4, c = (i & 15) * 8;
            *(uint4*)&sA[r * LDA + c] = A4[i];
        }
    } else {
        const float4* A4 = (const float4*)((const float*)Aptr + (size_t)row0 * DF);
        for (int i = tid; i < 128 * DF / 4; i += 256) {
            float4 v = A4[i];
            int r = i >> 5, c = (i & 31) * 4;
            __half2* d = (__half2*)&sA[r * LDA + c];
            d[0] = __floats2half2_rn(v.x, v.y);
            d[1] = __floats2half2_rn(v.z, v.w);
        }
    }
    __syncthreads();

    int warp = tid >> 5, lane = tid & 31;
    int wrow = warp * 16;

    float acc[16][4];
#pragma unroll
    for (int t = 0; t < 16; t++)
#pragma unroll
        for (int c = 0; c < 4; c++) acc[t][c] = 0.f;

    // per-lane ldmatrix base addresses
    unsigned aBase = (unsigned)__cvta_generic_to_shared(
        &sA[(wrow + (lane & 15)) * LDA + (lane >> 4) * 8]);
    int bk = (lane & 15);             // k row within k-step (0..15)
    int bn = (lane >> 4) * 8;         // n offset within 16-wide pair
    unsigned bBase = (unsigned)__cvta_generic_to_shared(&sB[bk * LDA + bn]);

#pragma unroll
    for (int k0 = 0; k0 < 8; k0++) {
        unsigned a0, a1, a2, a3;
        ldsm_x4(a0, a1, a2, a3, aBase + k0 * 32);  // 16 halves = 32 B along k
        unsigned bRow = bBase + (unsigned)(k0 * 16 * LDA * 2);
#pragma unroll
        for (int np = 0; np < 8; np++) {
            unsigned b0, b1, b2, b3;
            ldsm_x4t(b0, b1, b2, b3, bRow + np * 32);  // 16 cols = 32 B along n
            MMA16816(acc[2 * np],     a0, a1, a2, a3, b0, b1);
            MMA16816(acc[2 * np + 1], a0, a1, a2, a3, b2, b3);
        }
    }
    __syncthreads();  // done reading sA/sB; reuse sA as C staging

    // write accum -> sA (fp16), conflict-free STS.32
    int crow = wrow + (lane >> 2);
    int ccol = 2 * (lane & 3);
#pragma unroll
    for (int t = 0; t < 16; t++) {
        *(__half2*)&sA[crow * LDA + t * 8 + ccol]       = __floats2half2_rn(acc[t][0], acc[t][1]);
        *(__half2*)&sA[(crow + 8) * LDA + t * 8 + ccol] = __floats2half2_rn(acc[t][2], acc[t][3]);
    }
    __syncthreads();

    // coalesced copy to global
    for (int i = tid; i < 128 * DF / 8; i += 256) {
        int r = i >> 4, c = (i & 15) * 8;
        *(uint4*)&C[(size_t)(row0 + r) * DF + c] = *(const uint4*)&sA[r * LDA + c];
    }
}

// ---------------- segment aggregation (gather, one warp per segment) -------
template<int OUT_HALF, int RELU, int HAS_BIAS>
__global__ void k_agg(const __half* __restrict__ src, void* __restrict__ dst,
                      const int* __restrict__ off, const int* __restrict__ idx,
                      const float* __restrict__ scale, const float* __restrict__ bias,
                      int nseg) {
    int gwarp = (blockIdx.x * blockDim.x + threadIdx.x) >> 5;
    int lane = threadIdx.x & 31;
    if (gwarp >= nseg) return;
    int s = off[gwarp], e = off[gwarp + 1];
    const uint2* s2 = (const uint2*)src;

    float4 a0 = make_float4(0.f, 0.f, 0.f, 0.f);
    float4 a1 = make_float4(0.f, 0.f, 0.f, 0.f);
    int j = s;
    for (; j + 1 < e; j += 2) {
        int r0 = idx[j];
        int r1 = idx[j + 1];
        uint2 u0 = s2[(size_t)r0 * 32 + lane];
        uint2 u1 = s2[(size_t)r1 * 32 + lane];
        float2 f00 = __half22float2(*(const __half2*)&u0.x);
        float2 f01 = __half22float2(*(const __half2*)&u0.y);
        float2 f10 = __half22float2(*(const __half2*)&u1.x);
        float2 f11 = __half22float2(*(const __half2*)&u1.y);
        a0.x += f00.x; a0.y += f00.y; a0.z += f01.x; a0.w += f01.y;
        a1.x += f10.x; a1.y += f10.y; a1.z += f11.x; a1.w += f11.y;
    }
    if (j < e) {
        int r = idx[j];
        uint2 u = s2[(size_t)r * 32 + lane];
        float2 f0 = __half22float2(*(const __half2*)&u.x);
        float2 f1 = __half22float2(*(const __half2*)&u.y);
        a0.x += f0.x; a0.y += f0.y; a0.z += f1.x; a0.w += f1.y;
    }
    float sc = scale[gwarp];
    float4 o;
    o.x = (a0.x + a1.x) * sc;
    o.y = (a0.y + a1.y) * sc;
    o.z = (a0.z + a1.z) * sc;
    o.w = (a0.w + a1.w) * sc;
    if (HAS_BIAS) {
        float4 bb = ((const float4*)bias)[lane];
        o.x += bb.x; o.y += bb.y; o.z += bb.z; o.w += bb.w;
    }
    if (RELU) {
        o.x = fmaxf(o.x, 0.f); o.y = fmaxf(o.y, 0.f);
        o.z = fmaxf(o.z, 0.f); o.w = fmaxf(o.w, 0.f);
    }
    if (OUT_HALF) {
        __half2 h01 = __floats2half2_rn(o.x, o.y);
        __half2 h23 = __floats2half2_rn(o.z, o.w);
        uint2 st;
        st.x = *(unsigned*)&h01;
        st.y = *(unsigned*)&h23;
        ((uint2*)dst)[(size_t)gwarp * 32 + lane] = st;
    } else {
        ((float4*)dst)[(size_t)gwarp * 32 + lane] = o;
    }
}

// ---------------- launch ---------------------------------------------------
extern "C" void kernel_launch(void* const* d_in, const int* in_sizes, int n_in,
                              void* d_out, int out_size) {
    const float* x   = (const float*)d_in[0];
    const int*   hei = (const int*)d_in[1];
    const float* w   = (const float*)d_in[2];
    const float* W1  = (const float*)d_in[3];
    const float* b1  = (const float*)d_in[4];
    const float* W2  = (const float*)d_in[5];
    const float* b2  = (const float*)d_in[6];
    float* out = (float*)d_out;

    const int* nidx = hei;
    const int* eidx = hei + NNZ_CNT;

    int *p_off_e, *p_off_n, *p_csr_e, *p_csr_n;
    float *p_se, *p_dinv;
    __half *p_y, *p_ef, *p_h;
    cudaGetSymbolAddress((void**)&p_off_e, g_off_e);
    cudaGetSymbolAddress((void**)&p_off_n, g_off_n);
    cudaGetSymbolAddress((void**)&p_csr_e, g_csr_e);
    cudaGetSymbolAddress((void**)&p_csr_n, g_csr_n);
    cudaGetSymbolAddress((void**)&p_y,    g_y_h);
    cudaGetSymbolAddress((void**)&p_ef,   g_ef_h);
    cudaGetSymbolAddress((void**)&p_h,    g_h_h);
    cudaGetSymbolAddress((void**)&p_se,   g_se);
    cudaGetSymbolAddress((void**)&p_dinv, g_dinv);

    const int GEMM_SMEM = 2 * 128 * LDA * 2;  // 69632 B
    cudaFuncSetAttribute(k_gemm_mma<0>, cudaFuncAttributeMaxDynamicSharedMemorySize, GEMM_SMEM);
    cudaFuncSetAttribute(k_gemm_mma<1>, cudaFuncAttributeMaxDynamicSharedMemorySize, GEMM_SMEM);

    // -------- shared preprocessing -----------------------------------------
    k_zero<<<256, 256>>>();
    k_hist<<<NNZ_CNT / 256, 256>>>(nidx, eidx, w);
    k_scan1<<<128, 1024>>>();
    k_scan2<<<1, 128>>>();
    k_scan3<<<128, 1024>>>(w);
    k_build<<<NNZ_CNT / 256, 256>>>(nidx, eidx);

    const int AGG_BLOCKS = N_NODES / 8;  // 8 warps per 256-thread block

    // -------- layer 1 ------------------------------------------------------
    k_gemm_mma<0><<<N_NODES / 128, 256, GEMM_SMEM>>>(x, W1, p_y);
    k_agg<1, 0, 0><<<AGG_BLOCKS, 256>>>(p_y, p_ef, p_off_e, p_csr_e, p_se, nullptr, N_EDGES);
    k_agg<1, 1, 1><<<AGG_BLOCKS, 256>>>(p_ef, p_h, p_off_n, p_csr_n, p_dinv, b1, N_NODES);

    // -------- layer 2 ------------------------------------------------------
    k_gemm_mma<1><<<N_NODES / 128, 256, GEMM_SMEM>>>(p_h, W2, p_y);
    k_agg<1, 0, 0><<<AGG_BLOCKS, 256>>>(p_y, p_ef, p_off_e, p_csr_e, p_se, nullptr, N_EDGES);
    k_agg<0, 0, 1><<<AGG_BLOCKS, 256>>>(p_ef, out, p_off_n, p_csr_n, p_dinv, b2, N_NODES);
}